// round 8
// baseline (speedup 1.0000x reference)
#include <cuda_runtime.h>
#include <cuda_fp16.h>
#include <cstdint>

typedef uint32_t u32;

// ====================== problem constants ======================
constexpr int T_LEN = 4000;
constexpr int NT    = 413;
constexpr int NE    = 412;
constexpr int OFF   = 206;              // xe[u] = x_ext[u + 206]
constexpr int S_LEN = T_LEN + NT;       // 4413
constexpr int NROWS = 4096;

constexpr int KTOT  = 576;              // K padded (need 540)
constexpr int KC    = 64;               // K chunk
constexpr int NCHUNK = KTOT / KC;       // 9
constexpr int XE_W  = T_LEN + KTOT;     // 4576
constexpr int MT    = 128;              // GEMM M (rows r)
constexpr int NTT   = 128;              // GEMM N (t positions)
constexpr int N_TTILE = (T_LEN + NTT - 1) / NTT;  // 32
constexpr int N_RBLK  = NROWS / MT;               // 32
constexpr int THREADS = 256;

constexpr float H_SCALE = 512.0f;       // keep fp16 taps normal-range
constexpr float INV_H_SCALE = 1.0f / 512.0f;

// smem: per stage 2 tiles (A = xe rows, B = Toeplitz), 128 rows x 64 fp16, pitch 144B
constexpr int PITCHB      = 144;
constexpr int TILE_BYTES  = 128 * PITCHB;       // 18432
constexpr int STAGE_BYTES = 2 * TILE_BYTES;     // 36864
constexpr int NSTAGE      = 3;
constexpr int SMEM_DYN    = NSTAGE * STAGE_BYTES;   // 110592

// ====================== device scratch ======================
__device__ __align__(16) __half g_xe[(size_t)NROWS * XE_W];
__device__ __align__(16) __half g_B[NTT * KTOT];

// ====================== PTX helpers (family-agnostic, sm_80+) ======================
__device__ __forceinline__ u32 smem_u32(const void* p) {
    u32 a;
    asm("{ .reg .u64 t; cvta.to.shared.u64 t, %1; cvt.u32.u64 %0, t; }" : "=r"(a) : "l"(p));
    return a;
}
#define CP_ASYNC16(dst, src) \
    asm volatile("cp.async.cg.shared.global [%0], [%1], 16;" :: "r"(dst), "l"(src))
#define CP_COMMIT() asm volatile("cp.async.commit_group;" ::: "memory")

#define LDSM4(r, addr) \
    asm volatile("ldmatrix.sync.aligned.m8n8.x4.shared.b16 {%0,%1,%2,%3}, [%4];" \
        : "=r"((r)[0]), "=r"((r)[1]), "=r"((r)[2]), "=r"((r)[3]) : "r"(addr))

#define MMA16816(d, a, b) \
    asm volatile("mma.sync.aligned.m16n8k16.row.col.f32.f16.f16.f32 " \
        "{%0,%1,%2,%3}, {%4,%5,%6,%7}, {%8,%9}, {%0,%1,%2,%3};" \
        : "+f"((d)[0]), "+f"((d)[1]), "+f"((d)[2]), "+f"((d)[3]) \
        : "r"((a)[0]), "r"((a)[1]), "r"((a)[2]), "r"((a)[3]), \
          "r"((b)[0]), "r"((b)[1]))

// ====================== fused prep kernel ======================
__device__ __forceinline__ float xext_val(const float* __restrict__ xr, int e) {
    if (e < NE)         return 2.0f * xr[0]         - xr[NE - e];
    if (e < NE + T_LEN) return xr[e - NE];
    return 2.0f * xr[T_LEN - 1] - xr[2 * T_LEN - 2 + NE - e];
}

// blocks [0, NROWS): xe row build with 16B stores.
// blocks [NROWS, ...): Toeplitz B[n][k] = hrev[k-n] * H_SCALE.
__global__ void prep_kernel(const float* __restrict__ x, const float* __restrict__ h) {
    const int b = blockIdx.x;
    if (b < NROWS) {
        const float* xr = x + (size_t)b * T_LEN;
        __half* dst = g_xe + (size_t)b * XE_W;
        for (int seg = threadIdx.x; seg < XE_W / 8; seg += blockDim.x) {
            const int u0 = seg * 8;
            __half hv[8];
            #pragma unroll
            for (int q = 0; q < 8; q++) {
                int u = u0 + q;
                float v = (u < S_LEN) ? xext_val(xr, u + OFF) : 0.0f;
                hv[q] = __float2half(v);
            }
            *reinterpret_cast<uint4*>(dst + u0) = *reinterpret_cast<const uint4*>(hv);
        }
    } else {
        int idx = (b - NROWS) * blockDim.x + threadIdx.x;
        if (idx < NTT * KTOT) {
            int n = idx / KTOT, k = idx % KTOT;
            int j = k - n;
            float v = (j >= 0 && j < NT) ? h[NT - 1 - j] * H_SCALE : 0.0f;
            g_B[idx] = __float2half(v);
        }
    }
}
constexpr int PREP_B_BLOCKS = (NTT * KTOT + 255) / 256;   // 288

// ====================== GEMM kernel (mma.sync fp16, 3-stage pipeline) ======================
__global__ void __launch_bounds__(THREADS, 2)
fir_gemm_kernel(float* __restrict__ out) {
    extern __shared__ __align__(1024) char smem[];
    const int tid = threadIdx.x;
    const int wid = tid >> 5;
    const int lid = tid & 31;
    const int wm  = wid & 3;        // 0..3 -> row slice of 32
    const int wn  = wid >> 2;       // 0..1 -> t slice of 64
    const int t0    = blockIdx.x * NTT;
    const int rbase = blockIdx.y * MT;

    // Toeplitz band: warp-group wn skips the chunk whose B rows are all zero:
    // wn=0 -> chunk 8 (k-n > 412 everywhere), wn=1 -> chunk 0 (k < n everywhere).
    const int skipc = (wn == 0) ? (NCHUNK - 1) : 0;

    const u32 sb = smem_u32(smem);

    // ---- precomputed staging addresses (chunk advance = +128 bytes on src) ----
    const char* xebase = (const char*)g_xe;
    const char* bbase  = (const char*)g_B;
    u32 asrc[4], adst[4], bsrc[4], bdst[4];
    #pragma unroll
    for (int it = 0; it < 4; it++) {
        {   // A (xe): idx in [0, 1024)
            int idx = it * THREADS + tid;
            int r = idx >> 3, seg = idx & 7;
            asrc[it] = (u32)(((size_t)(rbase + r) * XE_W + t0 + seg * 8) * 2);
            adst[it] = r * PITCHB + seg * 16;
        }
        {   // B (Toeplitz): idx in [1024, 2048)
            int idx = it * THREADS + tid;     // reuse same within-tile pattern
            int r = idx >> 3, seg = idx & 7;
            bsrc[it] = (u32)(((size_t)r * KTOT + seg * 8) * 2);
            bdst[it] = TILE_BYTES + r * PITCHB + seg * 16;
        }
    }

    auto stage = [&](int koff, u32 dbase) {
        #pragma unroll
        for (int it = 0; it < 4; it++)
            CP_ASYNC16(dbase + adst[it], xebase + asrc[it] + koff);
        #pragma unroll
        for (int it = 0; it < 4; it++)
            CP_ASYNC16(dbase + bdst[it], bbase + bsrc[it] + koff);
    };

    // ---- per-thread ldmatrix base addresses (stage 0) ----
    u32 aAddr[2];
    #pragma unroll
    for (int i = 0; i < 2; i++)
        aAddr[i] = sb + (wm * 32 + i * 16 + (lid & 15)) * PITCHB + ((lid >> 4) * 16);
    u32 bAddr[4];
    #pragma unroll
    for (int jp = 0; jp < 4; jp++)
        bAddr[jp] = sb + TILE_BYTES +
                    (wn * 64 + jp * 16 + ((lid >> 4) * 8) + (lid & 7)) * PITCHB +
                    (((lid >> 3) & 1) * 16);

    float acc[2][8][4];
    #pragma unroll
    for (int i = 0; i < 2; i++)
        #pragma unroll
        for (int j = 0; j < 8; j++)
            #pragma unroll
            for (int q = 0; q < 4; q++) acc[i][j][q] = 0.0f;

    stage(0, sb);
    CP_COMMIT();
    stage(128, sb + STAGE_BYTES);
    CP_COMMIT();

    int s = 0;
    #pragma unroll 1
    for (int c = 0; c < NCHUNK; c++) {
        if (c == NCHUNK - 1)
            asm volatile("cp.async.wait_group 0;" ::: "memory");
        else
            asm volatile("cp.async.wait_group 1;" ::: "memory");
        __syncthreads();   // single barrier per chunk: protects both read of chunk c
                           // and overwrite of buffer (c-1)%3 by stage(c+2) below

        if (c + 2 < NCHUNK) {
            int s2 = s + 2; if (s2 >= NSTAGE) s2 -= NSTAGE;
            stage((c + 2) * 128, sb + s2 * STAGE_BYTES);
            CP_COMMIT();
        }

        if (c != skipc) {
            const u32 soff = s * STAGE_BYTES;
            #pragma unroll
            for (int ks = 0; ks < KC / 16; ks++) {
                const u32 kb = soff + ks * 32;
                u32 a[2][4];
                u32 b[8][2];
                #pragma unroll
                for (int i = 0; i < 2; i++) LDSM4(a[i], aAddr[i] + kb);
                #pragma unroll
                for (int jp = 0; jp < 4; jp++) {
                    u32 r4[4];
                    LDSM4(r4, bAddr[jp] + kb);
                    b[jp*2][0]   = r4[0]; b[jp*2][1]   = r4[1];
                    b[jp*2+1][0] = r4[2]; b[jp*2+1][1] = r4[3];
                }
                #pragma unroll
                for (int i = 0; i < 2; i++)
                    #pragma unroll
                    for (int j = 0; j < 8; j++) MMA16816(acc[i][j], a[i], b[j]);
            }
        }
        s++; if (s == NSTAGE) s = 0;
    }

    // ---- epilogue: D[m=r][n=t] -> out[r*T_LEN + t], undo H_SCALE ----
    #pragma unroll
    for (int i = 0; i < 2; i++) {
        int r0 = rbase + wm * 32 + i * 16 + (lid >> 2);
        #pragma unroll
        for (int j = 0; j < 8; j++) {
            int t = t0 + wn * 64 + j * 8 + 2 * (lid & 3);
            if (t < T_LEN) {
                *reinterpret_cast<float2*>(out + (size_t)r0 * T_LEN + t) =
                    make_float2(acc[i][j][0] * INV_H_SCALE, acc[i][j][1] * INV_H_SCALE);
                *reinterpret_cast<float2*>(out + (size_t)(r0 + 8) * T_LEN + t) =
                    make_float2(acc[i][j][2] * INV_H_SCALE, acc[i][j][3] * INV_H_SCALE);
            }
        }
    }
}

// ====================== launch ======================
extern "C" void kernel_launch(void* const* d_in, const int* in_sizes, int n_in,
                              void* d_out, int out_size)
{
    const float* x = (const float*)d_in[0];   // [64, 64, 4000] f32
    const float* h = (const float*)d_in[1];   // [413] f32
    float* out = (float*)d_out;

    cudaFuncSetAttribute(fir_gemm_kernel,
                         cudaFuncAttributeMaxDynamicSharedMemorySize, SMEM_DYN);

    prep_kernel<<<NROWS + PREP_B_BLOCKS, 256>>>(x, h);
    fir_gemm_kernel<<<dim3(N_TTILE, N_RBLK), THREADS, SMEM_DYN>>>(out);
}

// round 9
// speedup vs baseline: 1.0971x; 1.0971x over previous
#include <cuda_runtime.h>
#include <cuda_fp16.h>
#include <cstdint>

typedef uint32_t u32;

// ====================== problem constants ======================
constexpr int T_LEN = 4000;
constexpr int NT    = 413;
constexpr int NE    = 412;
constexpr int OFF   = 206;              // xe[u] = x_ext[u + 206]
constexpr int S_LEN = T_LEN + NT;       // 4413
constexpr int NROWS = 4096;

constexpr int KTOT  = 576;              // K padded (need 540)
constexpr int KC    = 64;               // K chunk
constexpr int NCHUNK = KTOT / KC;       // 9
constexpr int XE_W  = T_LEN + KTOT;     // 4576
constexpr int MT    = 128;              // GEMM M (rows r)
constexpr int NTT   = 128;              // GEMM N (t positions)
constexpr int N_TTILE = (T_LEN + NTT - 1) / NTT;  // 32
constexpr int N_RBLK  = NROWS / MT;               // 32
constexpr int THREADS = 256;

constexpr float H_SCALE = 512.0f;
constexpr float INV_H_SCALE = 1.0f / 512.0f;

// A staging: 128 rows x 64 fp16, pitch 144B, 3 stages.
constexpr int PITCHB   = 144;
constexpr int STAGE_A  = 128 * PITCHB;          // 18432
constexpr int NSTAGE   = 3;
// Diagonal bank: B tile for diagonal d depends only on d = k - n.
// Tiles for d = -120 + 8*t, t in [0, 86). Each tile = 16 rows x 16B
// (rows 0-7: n0..7 x k0..7 ; rows 8-15: n0..7 x k8..15) = 256B.
constexpr int BANK_TILES = 86;
constexpr int BANK_BYTES = BANK_TILES * 256;    // 22016
constexpr int BANK_HALVES = BANK_TILES * 128;   // 11008
constexpr int SMEM_DYN  = NSTAGE * STAGE_A + BANK_BYTES;   // 77312

// ====================== device scratch ======================
__device__ __align__(16) __half g_xe[(size_t)NROWS * XE_W];
__device__ __align__(16) __half g_Bd[BANK_HALVES];

// ====================== PTX helpers (family-agnostic, sm_80+) ======================
__device__ __forceinline__ u32 smem_u32(const void* p) {
    u32 a;
    asm("{ .reg .u64 t; cvta.to.shared.u64 t, %1; cvt.u32.u64 %0, t; }" : "=r"(a) : "l"(p));
    return a;
}
#define CP_ASYNC16(dst, src) \
    asm volatile("cp.async.cg.shared.global [%0], [%1], 16;" :: "r"(dst), "l"(src))
#define CP_COMMIT() asm volatile("cp.async.commit_group;" ::: "memory")

#define LDSM4(r, addr) \
    asm volatile("ldmatrix.sync.aligned.m8n8.x4.shared.b16 {%0,%1,%2,%3}, [%4];" \
        : "=r"((r)[0]), "=r"((r)[1]), "=r"((r)[2]), "=r"((r)[3]) : "r"(addr))

#define MMA16816(d, a, b0, b1) \
    asm volatile("mma.sync.aligned.m16n8k16.row.col.f32.f16.f16.f32 " \
        "{%0,%1,%2,%3}, {%4,%5,%6,%7}, {%8,%9}, {%0,%1,%2,%3};" \
        : "+f"((d)[0]), "+f"((d)[1]), "+f"((d)[2]), "+f"((d)[3]) \
        : "r"((a)[0]), "r"((a)[1]), "r"((a)[2]), "r"((a)[3]), \
          "r"(b0), "r"(b1))

// ====================== fused prep kernel ======================
__device__ __forceinline__ float xext_val(const float* __restrict__ xr, int e) {
    if (e < NE)         return 2.0f * xr[0]         - xr[NE - e];
    if (e < NE + T_LEN) return xr[e - NE];
    return 2.0f * xr[T_LEN - 1] - xr[2 * T_LEN - 2 + NE - e];
}

// blocks [0, NROWS): xe row build (16B stores).
// blocks [NROWS, ...): diagonal bank. Tile t has d = 8t - 120; row r, col kk:
//   n' = r&7, k' = kk + (r>=8 ? 8 : 0), value = hrev[d + k' - n'] * H_SCALE.
__global__ void prep_kernel(const float* __restrict__ x, const float* __restrict__ h) {
    const int b = blockIdx.x;
    if (b < NROWS) {
        const float* xr = x + (size_t)b * T_LEN;
        __half* dst = g_xe + (size_t)b * XE_W;
        for (int seg = threadIdx.x; seg < XE_W / 8; seg += blockDim.x) {
            const int u0 = seg * 8;
            __half hv[8];
            #pragma unroll
            for (int q = 0; q < 8; q++) {
                int u = u0 + q;
                float v = (u < S_LEN) ? xext_val(xr, u + OFF) : 0.0f;
                hv[q] = __float2half(v);
            }
            *reinterpret_cast<uint4*>(dst + u0) = *reinterpret_cast<const uint4*>(hv);
        }
    } else {
        int idx = (b - NROWS) * blockDim.x + threadIdx.x;
        if (idx < BANK_HALVES) {
            int t  = idx >> 7;
            int r  = (idx >> 3) & 15;
            int kk = idx & 7;
            int np = r & 7;
            int kp = kk + ((r >= 8) ? 8 : 0);
            int j  = (8 * t - 120) + kp - np;       // hrev index
            float v = (j >= 0 && j < NT) ? h[NT - 1 - j] * H_SCALE : 0.0f;
            g_Bd[idx] = __float2half(v);
        }
    }
}
constexpr int PREP_BANK_BLOCKS = (BANK_HALVES + 255) / 256;   // 43

// ====================== GEMM kernel ======================
__global__ void __launch_bounds__(THREADS, 2)
fir_gemm_kernel(float* __restrict__ out) {
    extern __shared__ __align__(1024) char smem[];
    const int tid = threadIdx.x;
    const int wid = tid >> 5;
    const int lid = tid & 31;
    const int wm  = wid & 3;        // row slice of 32
    const int wn  = wid >> 2;       // t slice of 64
    const int t0    = blockIdx.x * NTT;
    const int rbase = blockIdx.y * MT;

    // chunk where this warp-group's entire B band is zero
    const int skipc = (wn == 0) ? (NCHUNK - 1) : 0;

    const u32 sb   = smem_u32(smem);
    const u32 bank = sb + NSTAGE * STAGE_A;

    // ---- A staging addresses (4 x 16B per thread per chunk) ----
    const char* xebase = (const char*)g_xe;
    u32 asrc[4], adst[4];
    #pragma unroll
    for (int it = 0; it < 4; it++) {
        int idx = it * THREADS + tid;   // 0..1023
        int r = idx >> 3, seg = idx & 7;
        asrc[it] = (u32)(((size_t)(rbase + r) * XE_W + t0 + seg * 8) * 2);
        adst[it] = r * PITCHB + seg * 16;
    }
    auto stageA = [&](int c, u32 dbase) {
        const int koff = c * 128;
        #pragma unroll
        for (int it = 0; it < 4; it++)
            CP_ASYNC16(dbase + adst[it], xebase + asrc[it] + koff);
    };

    // ---- one-time bank load + first two A stages ----
    {
        const char* bdbase = (const char*)g_Bd;
        for (int i = tid; i < BANK_BYTES / 16; i += THREADS)
            CP_ASYNC16(bank + i * 16, bdbase + (size_t)i * 16);
    }
    stageA(0, sb);
    CP_COMMIT();                          // group: bank + chunk0
    stageA(1, sb + STAGE_A);
    CP_COMMIT();                          // group: chunk1

    // ---- ldmatrix bases ----
    u32 aRel[2];
    #pragma unroll
    for (int i = 0; i < 2; i++)
        aRel[i] = (wm * 32 + i * 16 + (lid & 15)) * PITCHB + ((lid >> 4) * 16);
    const u32 bLane = bank + lid * 16;

    float acc[2][8][4];
    #pragma unroll
    for (int i = 0; i < 2; i++)
        #pragma unroll
        for (int j = 0; j < 8; j++)
            #pragma unroll
            for (int q = 0; q < 4; q++) acc[i][j][q] = 0.0f;

    int s = 0;
    #pragma unroll 1
    for (int c = 0; c < NCHUNK; c++) {
        if (c == NCHUNK - 1)
            asm volatile("cp.async.wait_group 0;" ::: "memory");
        else
            asm volatile("cp.async.wait_group 1;" ::: "memory");
        __syncthreads();

        if (c + 2 < NCHUNK) {
            int s2 = s + 2; if (s2 >= NSTAGE) s2 -= NSTAGE;
            stageA(c + 2, sb + s2 * STAGE_A);
            CP_COMMIT();
        }

        if (c != skipc) {
            // B diagonals for this warp-chunk: global tile idx = 8(c-wn)+8 + rel,
            // rel = 2*ks - j + 7 in [0,13]. 7 LDSM.x4 fetch tiles pairwise.
            u32 bf[14][2];
            const u32 bb = bLane + (u32)((c - wn) * 2048 + 2048);
            #pragma unroll
            for (int p = 0; p < 7; p++) {
                u32 r4[4];
                LDSM4(r4, bb + p * 512);
                bf[2*p][0]   = r4[0]; bf[2*p][1]   = r4[1];
                bf[2*p+1][0] = r4[2]; bf[2*p+1][1] = r4[3];
            }
            const u32 abase = sb + s * STAGE_A;
            #pragma unroll
            for (int ks = 0; ks < KC / 16; ks++) {
                u32 a[2][4];
                #pragma unroll
                for (int i = 0; i < 2; i++)
                    LDSM4(a[i], abase + aRel[i] + ks * 32);
                #pragma unroll
                for (int i = 0; i < 2; i++)
                    #pragma unroll
                    for (int j = 0; j < 8; j++) {
                        const int rel = 2 * ks - j + 7;
                        MMA16816(acc[i][j], a[i], bf[rel][0], bf[rel][1]);
                    }
            }
        }
        s++; if (s == NSTAGE) s = 0;
    }

    // ---- epilogue: D[m=r][n=t] -> out[r*T_LEN + t], undo H_SCALE ----
    #pragma unroll
    for (int i = 0; i < 2; i++) {
        int r0 = rbase + wm * 32 + i * 16 + (lid >> 2);
        #pragma unroll
        for (int j = 0; j < 8; j++) {
            int t = t0 + wn * 64 + j * 8 + 2 * (lid & 3);
            if (t < T_LEN) {
                *reinterpret_cast<float2*>(out + (size_t)r0 * T_LEN + t) =
                    make_float2(acc[i][j][0] * INV_H_SCALE, acc[i][j][1] * INV_H_SCALE);
                *reinterpret_cast<float2*>(out + (size_t)(r0 + 8) * T_LEN + t) =
                    make_float2(acc[i][j][2] * INV_H_SCALE, acc[i][j][3] * INV_H_SCALE);
            }
        }
    }
}

// ====================== launch ======================
extern "C" void kernel_launch(void* const* d_in, const int* in_sizes, int n_in,
                              void* d_out, int out_size)
{
    const float* x = (const float*)d_in[0];   // [64, 64, 4000] f32
    const float* h = (const float*)d_in[1];   // [413] f32
    float* out = (float*)d_out;

    cudaFuncSetAttribute(fir_gemm_kernel,
                         cudaFuncAttributeMaxDynamicSharedMemorySize, SMEM_DYN);

    prep_kernel<<<NROWS + PREP_BANK_BLOCKS, 256>>>(x, h);
    fir_gemm_kernel<<<dim3(N_TTILE, N_RBLK), THREADS, SMEM_DYN>>>(out);
}

// round 10
// speedup vs baseline: 1.1868x; 1.0817x over previous
#include <cuda_runtime.h>
#include <cuda_fp16.h>
#include <cstdint>

typedef uint32_t u32;

// ====================== problem constants ======================
constexpr int T_LEN = 4000;
constexpr int NT    = 413;
constexpr int NE    = 412;
constexpr int OFF   = 206;              // xe[u] = x_ext[u + 206]
constexpr int S_LEN = T_LEN + NT;       // 4413
constexpr int NROWS = 4096;

constexpr int KTOT  = 576;              // K padded (need 540)
constexpr int KC    = 64;               // K chunk
constexpr int NCHUNK = KTOT / KC;       // 9
constexpr int XE_W  = T_LEN + KTOT;     // 4576
constexpr int MT    = 128;              // GEMM M (rows r)
constexpr int NTT   = 128;              // GEMM N (t positions)
constexpr int N_TTILE = (T_LEN + NTT - 1) / NTT;  // 32
constexpr int N_RBLK  = NROWS / MT;               // 32
constexpr int THREADS = 256;

constexpr float H_SCALE = 512.0f;
constexpr float INV_H_SCALE = 1.0f / 512.0f;

// A staging: 128 rows x 64 fp16, pitch 144B, 3 stages.
constexpr int PITCHB   = 144;
constexpr int STAGE_A  = 128 * PITCHB;          // 18432
constexpr int NSTAGE   = 3;
// Diagonal bank: B tile for diagonal d = 8t - 120, t in [0,86). 256B/tile.
constexpr int BANK_TILES = 86;
constexpr int BANK_BYTES = BANK_TILES * 256;    // 22016
constexpr int BANK_HALVES = BANK_TILES * 128;
constexpr int SMEM_DYN  = NSTAGE * STAGE_A + BANK_BYTES;   // 77312

// band: tile t nonzero iff t in [14, 67]  (d0 in [-8, 416])
constexpr int TLO = 14, THI = 67;

// ====================== device scratch ======================
__device__ __align__(16) __half g_xe[(size_t)NROWS * XE_W];
__device__ __align__(16) __half g_Bd[BANK_HALVES];

// ====================== PTX helpers (family-agnostic, sm_80+) ======================
__device__ __forceinline__ u32 smem_u32(const void* p) {
    u32 a;
    asm("{ .reg .u64 t; cvta.to.shared.u64 t, %1; cvt.u32.u64 %0, t; }" : "=r"(a) : "l"(p));
    return a;
}
#define CP_ASYNC16(dst, src) \
    asm volatile("cp.async.cg.shared.global [%0], [%1], 16;" :: "r"(dst), "l"(src))
#define CP_COMMIT() asm volatile("cp.async.commit_group;" ::: "memory")

#define LDSM4(r, addr) \
    asm volatile("ldmatrix.sync.aligned.m8n8.x4.shared.b16 {%0,%1,%2,%3}, [%4];" \
        : "=r"((r)[0]), "=r"((r)[1]), "=r"((r)[2]), "=r"((r)[3]) : "r"(addr))

#define MMA16816(d, a, b0, b1) \
    asm volatile("mma.sync.aligned.m16n8k16.row.col.f32.f16.f16.f32 " \
        "{%0,%1,%2,%3}, {%4,%5,%6,%7}, {%8,%9}, {%0,%1,%2,%3};" \
        : "+f"((d)[0]), "+f"((d)[1]), "+f"((d)[2]), "+f"((d)[3]) \
        : "r"((a)[0]), "r"((a)[1]), "r"((a)[2]), "r"((a)[3]), \
          "r"(b0), "r"(b1))

// ====================== fused prep kernel ======================
__device__ __forceinline__ float xext_val(const float* __restrict__ xr, int e) {
    if (e < NE)         return 2.0f * xr[0]         - xr[NE - e];
    if (e < NE + T_LEN) return xr[e - NE];
    return 2.0f * xr[T_LEN - 1] - xr[2 * T_LEN - 2 + NE - e];
}

__global__ void prep_kernel(const float* __restrict__ x, const float* __restrict__ h) {
    const int b = blockIdx.x;
    if (b < NROWS) {
        const float* xr = x + (size_t)b * T_LEN;
        __half* dst = g_xe + (size_t)b * XE_W;
        for (int seg = threadIdx.x; seg < XE_W / 8; seg += blockDim.x) {
            const int u0 = seg * 8;
            __half hv[8];
            #pragma unroll
            for (int q = 0; q < 8; q++) {
                int u = u0 + q;
                float v = (u < S_LEN) ? xext_val(xr, u + OFF) : 0.0f;
                hv[q] = __float2half(v);
            }
            *reinterpret_cast<uint4*>(dst + u0) = *reinterpret_cast<const uint4*>(hv);
        }
    } else {
        int idx = (b - NROWS) * blockDim.x + threadIdx.x;
        if (idx < BANK_HALVES) {
            int t  = idx >> 7;
            int r  = (idx >> 3) & 15;
            int kk = idx & 7;
            int np = r & 7;
            int kp = kk + ((r >= 8) ? 8 : 0);
            int j  = (8 * t - 120) + kp - np;       // hrev index
            float v = (j >= 0 && j < NT) ? h[NT - 1 - j] * H_SCALE : 0.0f;
            g_Bd[idx] = __float2half(v);
        }
    }
}
constexpr int PREP_BANK_BLOCKS = (BANK_HALVES + 255) / 256;   // 43

// ====================== per-chunk compute, compile-time band skip ======================
template<int C, int WN>
__device__ __forceinline__ void compute_chunk(u32 abase, u32 bLane, const u32* aRel,
                                              float (&acc)[2][8][4]) {
    constexpr int B0 = (C - WN) * 8 + 8;       // bank tile index at rel=0
    if constexpr (B0 + 13 < TLO || B0 > THI) return;   // whole chunk dead

    u32 bf[14][2];
    const u32 bb = bLane + (u32)(B0 * 256);
    #pragma unroll
    for (int p = 0; p < 7; p++) {
        // pair (2p, 2p+1): load iff any tile in band
        if (B0 + 2 * p + 1 >= TLO && B0 + 2 * p <= THI) {
            u32 r4[4];
            LDSM4(r4, bb + p * 512);
            bf[2*p][0]   = r4[0]; bf[2*p][1]   = r4[1];
            bf[2*p+1][0] = r4[2]; bf[2*p+1][1] = r4[3];
        }
    }
    #pragma unroll
    for (int ks = 0; ks < 4; ks++) {
        // any surviving j? t = B0 + 2ks - j + 7, j in [0,7] -> t in [B0+2ks, B0+2ks+7]
        if (B0 + 2 * ks + 7 >= TLO && B0 + 2 * ks <= THI) {
            u32 a[2][4];
            #pragma unroll
            for (int i = 0; i < 2; i++)
                LDSM4(a[i], abase + aRel[i] + ks * 32);
            #pragma unroll
            for (int i = 0; i < 2; i++)
                #pragma unroll
                for (int j = 0; j < 8; j++) {
                    const int t = B0 + 2 * ks - j + 7;
                    if (t >= TLO && t <= THI)
                        MMA16816(acc[i][j], a[i], bf[2*ks - j + 7][0], bf[2*ks - j + 7][1]);
                }
        }
    }
}

// ====================== GEMM kernel ======================
__global__ void __launch_bounds__(THREADS, 2)
fir_gemm_kernel(float* __restrict__ out) {
    extern __shared__ __align__(1024) char smem[];
    const int tid = threadIdx.x;
    const int wid = tid >> 5;
    const int lid = tid & 31;
    const int wm  = wid & 3;        // row slice of 32
    const int wn  = wid >> 2;       // t slice of 64
    const int t0    = blockIdx.x * NTT;
    const int rbase = blockIdx.y * MT;

    const u32 sb   = smem_u32(smem);
    const u32 bank = sb + NSTAGE * STAGE_A;

    // ---- A staging addresses (4 x 16B per thread per chunk) ----
    const char* xebase = (const char*)g_xe;
    u32 asrc[4], adst[4];
    #pragma unroll
    for (int it = 0; it < 4; it++) {
        int idx = it * THREADS + tid;   // 0..1023
        int r = idx >> 3, seg = idx & 7;
        asrc[it] = (u32)(((size_t)(rbase + r) * XE_W + t0 + seg * 8) * 2);
        adst[it] = r * PITCHB + seg * 16;
    }
    auto stageA = [&](int c, u32 dbase) {
        const int koff = c * 128;
        #pragma unroll
        for (int it = 0; it < 4; it++)
            CP_ASYNC16(dbase + adst[it], xebase + asrc[it] + koff);
    };

    // ---- one-time bank load + first two A stages ----
    {
        const char* bdbase = (const char*)g_Bd;
        for (int i = tid; i < BANK_BYTES / 16; i += THREADS)
            CP_ASYNC16(bank + i * 16, bdbase + (size_t)i * 16);
    }
    stageA(0, sb);
    CP_COMMIT();                          // group: bank + chunk0
    stageA(1, sb + STAGE_A);
    CP_COMMIT();                          // group: chunk1

    // ---- ldmatrix bases ----
    u32 aRel[2];
    #pragma unroll
    for (int i = 0; i < 2; i++)
        aRel[i] = (wm * 32 + i * 16 + (lid & 15)) * PITCHB + ((lid >> 4) * 16);
    const u32 bLane = bank + lid * 16;

    float acc[2][8][4];
    #pragma unroll
    for (int i = 0; i < 2; i++)
        #pragma unroll
        for (int j = 0; j < 8; j++)
            #pragma unroll
            for (int q = 0; q < 4; q++) acc[i][j][q] = 0.0f;

    // ---- fully unrolled chunk loop: barriers uniform, band skip constant-folded ----
#define GSTEP(C)                                                                         \
    do {                                                                                 \
        if ((C) == NCHUNK - 1) asm volatile("cp.async.wait_group 0;" ::: "memory");      \
        else                   asm volatile("cp.async.wait_group 1;" ::: "memory");      \
        __syncthreads();                                                                 \
        if ((C) + 2 < NCHUNK) {                                                          \
            stageA((C) + 2, sb + (((C) + 2) % NSTAGE) * STAGE_A);                        \
            CP_COMMIT();                                                                 \
        }                                                                                \
        const u32 abase_ = sb + ((C) % NSTAGE) * STAGE_A;                                \
        if (wn == 0) compute_chunk<(C), 0>(abase_, bLane, aRel, acc);                    \
        else         compute_chunk<(C), 1>(abase_, bLane, aRel, acc);                    \
    } while (0)

    GSTEP(0); GSTEP(1); GSTEP(2); GSTEP(3); GSTEP(4);
    GSTEP(5); GSTEP(6); GSTEP(7); GSTEP(8);
#undef GSTEP

    // ---- epilogue: D[m=r][n=t] -> out[r*T_LEN + t], undo H_SCALE ----
    #pragma unroll
    for (int i = 0; i < 2; i++) {
        int r0 = rbase + wm * 32 + i * 16 + (lid >> 2);
        #pragma unroll
        for (int j = 0; j < 8; j++) {
            int t = t0 + wn * 64 + j * 8 + 2 * (lid & 3);
            if (t < T_LEN) {
                *reinterpret_cast<float2*>(out + (size_t)r0 * T_LEN + t) =
                    make_float2(acc[i][j][0] * INV_H_SCALE, acc[i][j][1] * INV_H_SCALE);
                *reinterpret_cast<float2*>(out + (size_t)(r0 + 8) * T_LEN + t) =
                    make_float2(acc[i][j][2] * INV_H_SCALE, acc[i][j][3] * INV_H_SCALE);
            }
        }
    }
}

// ====================== launch ======================
extern "C" void kernel_launch(void* const* d_in, const int* in_sizes, int n_in,
                              void* d_out, int out_size)
{
    const float* x = (const float*)d_in[0];   // [64, 64, 4000] f32
    const float* h = (const float*)d_in[1];   // [413] f32
    float* out = (float*)d_out;

    cudaFuncSetAttribute(fir_gemm_kernel,
                         cudaFuncAttributeMaxDynamicSharedMemorySize, SMEM_DYN);

    prep_kernel<<<NROWS + PREP_BANK_BLOCKS, 256>>>(x, h);
    fir_gemm_kernel<<<dim3(N_TTILE, N_RBLK), THREADS, SMEM_DYN>>>(out);
}